// round 1
// baseline (speedup 1.0000x reference)
#include <cuda_runtime.h>
#include <stdint.h>

// ---------------------------------------------------------------------------
// VanDerWallsSurface: scatter point features into a 128^3 voxel grid.
//  out[b,x,y,z] = [max f0, min f1, mean f2] over points whose sphere covers
//  the voxel (within the 5x5x5 neighborhood of round(coords)), else zeros.
//
// Strategy:
//  - Order-preserving uint encodings make 0 the neutral element for all four
//    accumulators (max-key, min-key(as max), sum, count) -> scratch arrays are
//    zero-initialized statics and are re-zeroed lazily (touched entries only)
//    by the finalize kernel, so no bulk scratch init is ever needed.
//  - Kernel A fuses the mandatory 100MB output zeroing with the (tiny) atomic
//    scatter; the two halves of the grid are independent.
//  - Kernel B walks the compact touch-list, claims each voxel once via
//    atomicExch on cnt, writes its 3 output channels, and zeroes its scratch.
//  - Kernel C resets the list counter for the next (graph-replayed) call.
// ---------------------------------------------------------------------------

#define VOL        128
#define NB         4
#define NPTS       4096
#define NPOINTS    (NB * NPTS)            // 16384
#define KOFF       125                    // 5x5x5 offsets
#define NCAND      (NPOINTS * KOFF)       // 2,048,000 candidates
#define CAP        (1u << 21)             // 2,097,152 >= NCAND (list capacity)
#define TOTAL_VOX  (NB * VOL * VOL * VOL) // 8,388,608
#define TPB        256

#define ZERO_VEC    ((TOTAL_VOX * 3) / 4)   // 6,291,456 float4 stores
#define ZERO_BLOCKS (ZERO_VEC / TPB)        // 24,576
#define SCAT_BLOCKS (NCAND / TPB)           // 8,000
#define FIN_BLOCKS  (CAP / TPB)             // 8,192

// Scratch (zero-initialized at module load; kept zero by k_finalize).
__device__ unsigned int g_maxk[TOTAL_VOX];   // max-key of f0, neutral = 0
__device__ unsigned int g_mink[TOTAL_VOX];   // ~min-key of f1 (max form), neutral = 0
__device__ float        g_sum [TOTAL_VOX];   // sum f2, neutral = 0
__device__ unsigned int g_cnt [TOTAL_VOX];   // count, neutral = 0
__device__ unsigned int g_list[CAP];         // touched voxel ids (with dups)
__device__ unsigned int g_counter;           // appended entries this call

// Order-preserving float -> uint key. For any finite non-NaN f, fkey(f) > 0,
// so 0 is a valid "empty" sentinel for atomicMax accumulation.
__device__ __forceinline__ unsigned int fkey(float f) {
    unsigned int u = __float_as_uint(f);
    return (u & 0x80000000u) ? ~u : (u | 0x80000000u);
}
__device__ __forceinline__ float funkey(unsigned int k) {
    unsigned int u = (k & 0x80000000u) ? (k ^ 0x80000000u) : ~k;
    return __uint_as_float(u);
}

// Kernel A: blocks [0, ZERO_BLOCKS) zero d_out; blocks [ZERO_BLOCKS, ...)
// run the scatter. The two halves touch disjoint memory.
__global__ void __launch_bounds__(TPB) k_zero_scatter(
    const float4* __restrict__ cr,     // (B*N) x [cx, cy, cz, r]
    const float*  __restrict__ feat,   // (B*N) x 3
    float4*       __restrict__ out4)   // d_out viewed as float4
{
    int bid = blockIdx.x;
    if (bid < ZERO_BLOCKS) {
        out4[(size_t)bid * TPB + threadIdx.x] = make_float4(0.f, 0.f, 0.f, 0.f);
        return;
    }

    int t  = (bid - ZERO_BLOCKS) * TPB + threadIdx.x;  // candidate id
    int k  = t % KOFF;
    int pn = t / KOFF;                                  // linear point id

    float4 c = __ldg(cr + pn);  // 125 consecutive threads share -> L1 broadcast

    int ox = k / 25 - 2;
    int oy = (k / 5) % 5 - 2;
    int oz = k % 5 - 2;

    // jnp.round == round-half-to-even == rn conversions/rintf
    int vx = __float2int_rn(c.x) + ox;
    int vy = __float2int_rn(c.y) + oy;
    int vz = __float2int_rn(c.z) + oz;

    // Exact IEEE ops, left-to-right sum, matching the reference (no FMA
    // contraction that could flip sphere-boundary membership).
    float dx = __fsub_rn((float)vx, c.x);
    float dy = __fsub_rn((float)vy, c.y);
    float dz = __fsub_rn((float)vz, c.z);
    float d2 = __fadd_rn(__fadd_rn(__fmul_rn(dx, dx), __fmul_rn(dy, dy)),
                         __fmul_rn(dz, dz));

    float rr = __fdiv_rn(rintf(__fmul_rn(c.w, 1000.0f)), 1000.0f);
    float r2 = __fmul_rn(rr, rr);

    bool ok = (d2 <= r2)
            && ((unsigned)vx < VOL) && ((unsigned)vy < VOL) && ((unsigned)vz < VOL);
    if (!ok) return;

    unsigned e = (unsigned)((pn >> 12) * (VOL * VOL * VOL)
                            + ((vx * VOL + vy) * VOL + vz));

    const float* fp = feat + (size_t)pn * 3;
    float f0 = __ldg(fp + 0);
    float f1 = __ldg(fp + 1);
    float f2 = __ldg(fp + 2);

    atomicMax(&g_maxk[e], fkey(f0));
    atomicMax(&g_mink[e], ~fkey(f1));   // min via max of complemented key
    atomicAdd(&g_sum[e], f2);
    atomicAdd(&g_cnt[e], 1u);

    unsigned pos = atomicAdd(&g_counter, 1u) & (CAP - 1u);
    g_list[pos] = e;
}

// Kernel B: finalize touched voxels and restore scratch to all-zero.
__global__ void __launch_bounds__(TPB) k_finalize(float* __restrict__ out)
{
    unsigned i = blockIdx.x * TPB + threadIdx.x;
    if (i >= g_counter) return;             // only this call's entries

    unsigned e = g_list[i];
    if (g_cnt[e] == 0u) return;             // cheap pre-gate for duplicates
    unsigned c = atomicExch(&g_cnt[e], 0u); // claim (exactly one winner)
    if (c == 0u) return;

    unsigned mk = g_maxk[e];
    unsigned nk = g_mink[e];
    float    s  = g_sum[e];
    g_maxk[e] = 0u;                         // self-clean for next call
    g_mink[e] = 0u;
    g_sum[e]  = 0.0f;

    size_t o = (size_t)e * 3;
    out[o + 0] = funkey(mk);
    out[o + 1] = funkey(~nk);
    out[o + 2] = __fdiv_rn(s, (float)c);    // cnt >= 1 here (== max(cnt,1))
}

// Kernel C: reset list counter for the next call (can't be done racelessly
// inside k_finalize while other blocks are still bound-checking against it).
__global__ void k_reset() { g_counter = 0u; }

extern "C" void kernel_launch(void* const* d_in, const int* in_sizes, int n_in,
                              void* d_out, int out_size)
{
    const float4* cr   = (const float4*)d_in[0];  // coordinates_radii (B,N,4)
    const float*  feat = (const float*)d_in[1];   // features (B,N,3)
    float*        out  = (float*)d_out;           // (B,128,128,128,3) f32

    k_zero_scatter<<<ZERO_BLOCKS + SCAT_BLOCKS, TPB>>>(cr, feat, (float4*)out);
    k_finalize<<<FIN_BLOCKS, TPB>>>(out);
    k_reset<<<1, 1>>>();
}